// round 12
// baseline (speedup 1.0000x reference)
#include <cuda_runtime.h>
#include <cuda_fp16.h>
#include <math.h>
#include <stdint.h>

#define NT  4096
#define DM  512
#define NH  8
#define HD  64
#define DFF 1024

// ---------------- scratch (static device globals; no allocations) ----------
__device__ __half g_Q[NT * DM];      // fp16, 0.125-prescaled, pk16-packed
__device__ __half g_K[NT * DM];      // fp16, tile-contiguous packed (khalf_idx)
__device__ __half g_V[NT * DM];      // fp16, tile-contiguous packed (vhalf_idx)
__device__ __half g_x16[NT * DM];    // x packed fp16 (QKV GEMM A operand)
__device__ __half g_attn16[NT * DM]; // attention out packed fp16 (Wo A operand)
__device__ __half g_x116[NT * DM];   // LN1 out packed fp16 (W1 A operand)
__device__ __half g_hid16[NT * DFF]; // FF1 out packed fp16 (W2 A operand)
__device__ float  g_tmp[NT * DM];
__device__ float  g_x1[NT * DM];
// transposed fp16 weights, pk16-packed along k (B operands)
__device__ __half g_WqT[DM * DM];
__device__ __half g_WkT[DM * DM];
__device__ __half g_WvT[DM * DM];
__device__ __half g_WoT[DM * DM];
__device__ __half g_W1T[DFF * DM];
__device__ __half g_W2T[DM * DFF];

#define LOG2E 1.4426950408889634f

// ---------------- helpers ---------------------------------------------------
__host__ __device__ __forceinline__ int ppos(int r) {
    return ((r & 7) >> 1) * 4 + ((r >> 3) & 1) * 2 + (r & 1);
}

__device__ __forceinline__ size_t khalf_idx(int h, int tok, int dim) {
    int tl = tok & 63;
    int r = dim & 15;
    int c = (r >> 1) & 3, q = ((r >> 3) & 1) * 2 + (r & 1);
    int kkl = (dim >> 4) & 1, kkp = (dim >> 5) & 1;
    return (size_t)h * NT * 64 + (size_t)(tok >> 6) * 4096
         + tl * 64 + ((kkp ^ (tl & 1)) << 5) + c * 8 + kkl * 4 + q;
}
__device__ __forceinline__ size_t vhalf_idx(int h, int tok, int n) {
    int r = tok & 15;
    int c = (r >> 1) & 3, q = ((r >> 3) & 1) * 2 + (r & 1);
    int tkl = (tok >> 4) & 1, tkp = (tok >> 5) & 1;
    return (size_t)h * NT * 64 + (size_t)(tok >> 6) * 4096
         + n * 64 + ((tkp ^ (n & 1)) << 5) + c * 8 + tkl * 4 + q;
}

__device__ __forceinline__ uint32_t h2u(float lo, float hi) {
    uint32_t r;
    asm("cvt.rn.f16x2.f32 %0, %1, %2;" : "=r"(r) : "f"(hi), "f"(lo));
    return r;
}

__device__ __forceinline__ uint32_t ex2h2(uint32_t y) {
    uint32_t r;
    asm("ex2.approx.f16x2 %0, %1;" : "=r"(r) : "r"(y));
    return r;
}

__device__ __forceinline__ void mma16(float d[4],
                                      uint32_t a0, uint32_t a1, uint32_t a2, uint32_t a3,
                                      uint32_t b0, uint32_t b1) {
    asm("mma.sync.aligned.m16n8k16.row.col.f32.f16.f16.f32 "
        "{%0,%1,%2,%3}, {%4,%5,%6,%7}, {%8,%9}, {%0,%1,%2,%3};"
        : "+f"(d[0]), "+f"(d[1]), "+f"(d[2]), "+f"(d[3])
        : "r"(a0), "r"(a1), "r"(a2), "r"(a3), "r"(b0), "r"(b1));
}

__device__ __forceinline__ void cpa16(unsigned dst, const void* src) {
    asm volatile("cp.async.cg.shared.global [%0], [%1], 16;" :: "r"(dst), "l"(src));
}

__device__ __forceinline__ float fexp(float x) {
    float r;
    float y = x * LOG2E;
    asm("ex2.approx.f32 %0, %1;" : "=f"(r) : "f"(y));
    return r;
}

// ==================== fp16 GEMM: 128x128 tile, BK=32, 3-stage cp.async =====
// 8 warps (2x4), warp tile 64x32. smem/stage: A 8KB + B 8KB, both
// [kk(2)][row(128)][16 halves pk16]. 48KB total, 2 CTAs/SM.
template <int MODE>   // 0: fp32 out + bias; 1: bias + relu -> fp16 pk16 out
__global__ __launch_bounds__(256, 2) void gemm16(
    const __half* __restrict__ A16, const __half* __restrict__ Bt,
    const float* __restrict__ bias, void* __restrict__ Cout, int N, int K)
{
    __shared__ __align__(16) char smem[3 * 16384];
    const int tid = threadIdx.x;
    const int wid = tid >> 5, lane = tid & 31;
    const int g = lane >> 2, c = lane & 3;
    const int wm = (wid >> 2) * 64, wn = (wid & 3) * 32;
    const int m0 = blockIdx.y * 128, n0 = blockIdx.x * 128;
    const unsigned sb = (unsigned)__cvta_generic_to_shared(smem);

    float acc[4][4][4];
#pragma unroll
    for (int t = 0; t < 4; t++)
#pragma unroll
        for (int j = 0; j < 4; j++)
#pragma unroll
            for (int r = 0; r < 4; r++) acc[t][j][r] = 0.f;

    const int srow = tid >> 2, ssub = tid & 3;
    const unsigned sdst = (unsigned)(ssub >> 1) * 4096 + srow * 32 + (ssub & 1) * 16;
    const int soff = (ssub >> 1) * 16 + (ssub & 1) * 8;

    auto stage = [&](int kb, int st) {
        unsigned s0 = sb + st * 16384;
        const __half* ap = A16 + (size_t)(m0 + srow) * K + kb * 32 + soff;
        const __half* bp = Bt  + (size_t)(n0 + srow) * K + kb * 32 + soff;
        cpa16(s0 + sdst,               ap);
        cpa16(s0 + sdst + 2048,        ap + (size_t)64 * K);
        cpa16(s0 + 8192 + sdst,        bp);
        cpa16(s0 + 8192 + sdst + 2048, bp + (size_t)64 * K);
        asm volatile("cp.async.commit_group;" ::: "memory");
    };

    const int nk = K >> 5;
    stage(0, 0);
    stage(1, 1);

    for (int kb = 0; kb < nk; kb++) {
        if (kb + 1 < nk) {
            asm volatile("cp.async.wait_group 1;" ::: "memory");
        } else {
            asm volatile("cp.async.wait_group 0;" ::: "memory");
        }
        __syncthreads();
        if (kb + 2 < nk) stage(kb + 2, (kb + 2) % 3);

        const char* aB = smem + (kb % 3) * 16384;
        const char* bB = aB + 8192;
#pragma unroll
        for (int kk = 0; kk < 2; kk++) {
            uint32_t af[4][4];
#pragma unroll
            for (int t = 0; t < 4; t++) {
                uint2 r0 = *(const uint2*)(aB + kk * 4096 + (wm + 16 * t + g) * 32 + c * 8);
                uint2 r1 = *(const uint2*)(aB + kk * 4096 + (wm + 16 * t + g + 8) * 32 + c * 8);
                af[t][0] = r0.x; af[t][1] = r1.x; af[t][2] = r0.y; af[t][3] = r1.y;
            }
#pragma unroll
            for (int j = 0; j < 4; j++) {
                uint2 bv = *(const uint2*)(bB + kk * 4096 + (wn + 8 * j + g) * 32 + c * 8);
#pragma unroll
                for (int t = 0; t < 4; t++)
                    mma16(acc[t][j], af[t][0], af[t][1], af[t][2], af[t][3], bv.x, bv.y);
            }
        }
        __syncthreads();
    }

#pragma unroll
    for (int t = 0; t < 4; t++) {
        int row0 = m0 + wm + 16 * t + g;
#pragma unroll
        for (int j = 0; j < 4; j++) {
            int col = n0 + wn + 8 * j + 2 * c;
            float2 bv = *(const float2*)&bias[col];
            float v00 = acc[t][j][0] + bv.x, v01 = acc[t][j][1] + bv.y;
            float v10 = acc[t][j][2] + bv.x, v11 = acc[t][j][3] + bv.y;
            if (MODE == 0) {
                float* C = (float*)Cout;
                *(float2*)&C[(size_t)row0 * N + col]       = make_float2(v00, v01);
                *(float2*)&C[(size_t)(row0 + 8) * N + col] = make_float2(v10, v11);
            } else {
                v00 = fmaxf(v00, 0.f); v01 = fmaxf(v01, 0.f);
                v10 = fmaxf(v10, 0.f); v11 = fmaxf(v11, 0.f);
                __half* C = (__half*)Cout;
                size_t p = (size_t)row0 * N + (col & ~15) + ppos(col & 15);
                *(uint32_t*)&C[p]                 = h2u(v00, v01);
                *(uint32_t*)&C[p + (size_t)8 * N] = h2u(v10, v11);
            }
        }
    }
}

// ---------------- fused QKV GEMM (128x128 core, z selects projection) -------
__global__ __launch_bounds__(256, 2) void qkv16(
    const __half* __restrict__ x16,
    const __half* __restrict__ WqT, const float* __restrict__ bq, __half* __restrict__ Qo,
    const __half* __restrict__ WkT, const float* __restrict__ bk, __half* __restrict__ Ko,
    const __half* __restrict__ WvT, const float* __restrict__ bv, __half* __restrict__ Vo)
{
    __shared__ __align__(16) char smem[3 * 16384];
    const int z = blockIdx.z;
    const __half* Bt   = (z == 0) ? WqT : (z == 1) ? WkT : WvT;
    const float*  bias = (z == 0) ? bq  : (z == 1) ? bk  : bv;

    const int tid = threadIdx.x;
    const int wid = tid >> 5, lane = tid & 31;
    const int g = lane >> 2, c = lane & 3;
    const int wm = (wid >> 2) * 64, wn = (wid & 3) * 32;
    const int m0 = blockIdx.y * 128, n0 = blockIdx.x * 128;
    const unsigned sb = (unsigned)__cvta_generic_to_shared(smem);

    float acc[4][4][4];
#pragma unroll
    for (int t = 0; t < 4; t++)
#pragma unroll
        for (int j = 0; j < 4; j++)
#pragma unroll
            for (int r = 0; r < 4; r++) acc[t][j][r] = 0.f;

    const int srow = tid >> 2, ssub = tid & 3;
    const unsigned sdst = (unsigned)(ssub >> 1) * 4096 + srow * 32 + (ssub & 1) * 16;
    const int soff = (ssub >> 1) * 16 + (ssub & 1) * 8;

    auto stage = [&](int kb, int st) {
        unsigned s0 = sb + st * 16384;
        const __half* ap = x16 + (size_t)(m0 + srow) * DM + kb * 32 + soff;
        const __half* bp = Bt  + (size_t)(n0 + srow) * DM + kb * 32 + soff;
        cpa16(s0 + sdst,               ap);
        cpa16(s0 + sdst + 2048,        ap + (size_t)64 * DM);
        cpa16(s0 + 8192 + sdst,        bp);
        cpa16(s0 + 8192 + sdst + 2048, bp + (size_t)64 * DM);
        asm volatile("cp.async.commit_group;" ::: "memory");
    };

    const int nk = DM >> 5;
    stage(0, 0);
    stage(1, 1);

    for (int kb = 0; kb < nk; kb++) {
        if (kb + 1 < nk) {
            asm volatile("cp.async.wait_group 1;" ::: "memory");
        } else {
            asm volatile("cp.async.wait_group 0;" ::: "memory");
        }
        __syncthreads();
        if (kb + 2 < nk) stage(kb + 2, (kb + 2) % 3);

        const char* aB = smem + (kb % 3) * 16384;
        const char* bB = aB + 8192;
#pragma unroll
        for (int kk = 0; kk < 2; kk++) {
            uint32_t af[4][4];
#pragma unroll
            for (int t = 0; t < 4; t++) {
                uint2 r0 = *(const uint2*)(aB + kk * 4096 + (wm + 16 * t + g) * 32 + c * 8);
                uint2 r1 = *(const uint2*)(aB + kk * 4096 + (wm + 16 * t + g + 8) * 32 + c * 8);
                af[t][0] = r0.x; af[t][1] = r1.x; af[t][2] = r0.y; af[t][3] = r1.y;
            }
#pragma unroll
            for (int j = 0; j < 4; j++) {
                uint2 bv2 = *(const uint2*)(bB + kk * 4096 + (wn + 8 * j + g) * 32 + c * 8);
#pragma unroll
                for (int t = 0; t < 4; t++)
                    mma16(acc[t][j], af[t][0], af[t][1], af[t][2], af[t][3], bv2.x, bv2.y);
            }
        }
        __syncthreads();
    }

#pragma unroll
    for (int t = 0; t < 4; t++) {
        int row0 = m0 + wm + 16 * t + g;
#pragma unroll
        for (int j = 0; j < 4; j++) {
            int col = n0 + wn + 8 * j + 2 * c;
            float2 bvv = *(const float2*)&bias[col];
            float v00 = acc[t][j][0] + bvv.x, v01 = acc[t][j][1] + bvv.y;
            float v10 = acc[t][j][2] + bvv.x, v11 = acc[t][j][3] + bvv.y;
            if (z == 0) {
                size_t p0 = (size_t)row0 * DM + (col & ~15) + ppos(col & 15);
                *(uint32_t*)&Qo[p0]                  = h2u(v00 * 0.125f, v01 * 0.125f);
                *(uint32_t*)&Qo[p0 + (size_t)8 * DM] = h2u(v10 * 0.125f, v11 * 0.125f);
            } else if (z == 1) {
                int h = col >> 6, dl = col & 63;
                *(uint32_t*)&Ko[khalf_idx(h, row0,     dl)] = h2u(v00, v01);
                *(uint32_t*)&Ko[khalf_idx(h, row0 + 8, dl)] = h2u(v10, v11);
            } else {
                int h = col >> 6, dl = col & 63;
                Vo[vhalf_idx(h, row0,     dl)]     = __float2half_rn(v00);
                Vo[vhalf_idx(h, row0,     dl + 1)] = __float2half_rn(v01);
                Vo[vhalf_idx(h, row0 + 8, dl)]     = __float2half_rn(v10);
                Vo[vhalf_idx(h, row0 + 8, dl + 1)] = __float2half_rn(v11);
            }
        }
    }
}

// ---------------- pack x: fp32 [NT][DM] -> fp16 pk16 ------------------------
__global__ void __launch_bounds__(256) pack_x(
    const float* __restrict__ x, __half* __restrict__ o)
{
    int i = blockIdx.x * 256 + threadIdx.x;
    int row = i >> 5, grp = i & 31;
    const float* src = x + (size_t)row * DM + grp * 16;
    uint32_t u[8];
#pragma unroll
    for (int q = 0; q < 4; q++) {
        float4 v = *(const float4*)(src + q * 4);
        int d = q * 4;
        u[ppos(d) >> 1]     = h2u(v.x, v.y);
        u[ppos(d + 2) >> 1] = h2u(v.z, v.w);
    }
    __half* dst = o + (size_t)row * DM + grp * 16;
    *(uint4*)dst       = make_uint4(u[0], u[1], u[2], u[3]);
    *(uint4*)(dst + 8) = make_uint4(u[4], u[5], u[6], u[7]);
}

// ---------------- fused weight transpose: ONE launch for all 6 weights ------
__global__ void __launch_bounds__(256) transpose_all(
    const float* __restrict__ Wq, const float* __restrict__ Wk,
    const float* __restrict__ Wv, const float* __restrict__ Wo,
    const float* __restrict__ W1, const float* __restrict__ W2,
    __half* __restrict__ WqT, __half* __restrict__ WkT,
    __half* __restrict__ WvT, __half* __restrict__ WoT,
    __half* __restrict__ W1T, __half* __restrict__ W2T)
{
    __shared__ float t[32][33];
    const int z = blockIdx.z;
    const float* in; __half* outp; int K, N;
    switch (z) {
        case 0:  in = Wq; outp = WqT; K = DM;  N = DM;  break;
        case 1:  in = Wk; outp = WkT; K = DM;  N = DM;  break;
        case 2:  in = Wv; outp = WvT; K = DM;  N = DM;  break;
        case 3:  in = Wo; outp = WoT; K = DM;  N = DM;  break;
        case 4:  in = W1; outp = W1T; K = DM;  N = DFF; break;
        default: in = W2; outp = W2T; K = DFF; N = DM;  break;
    }
    const int n0 = blockIdx.x * 32, k0 = blockIdx.y * 32;
    if (n0 >= N || k0 >= K) return;
    const int tx = threadIdx.x & 31, ty = threadIdx.x >> 5;
#pragma unroll
    for (int i = 0; i < 4; i++)
        t[ty + 8 * i][tx] = in[(size_t)(k0 + ty + 8 * i) * N + n0 + tx];
    __syncthreads();
    if (tx < 16) {
#pragma unroll
        for (int i = 0; i < 4; i++) {
            int n = ty + 8 * i;
            int kl = 2 * tx;
            int pos = (kl & ~15) + ppos(kl & 15);
            *(uint32_t*)&outp[(size_t)(n0 + n) * K + k0 + pos] =
                h2u(t[kl][n], t[kl + 1][n]);
        }
    }
}

// ---------------- fp16 tensor-core flash attention --------------------------
// K/V AND bias cp.async double-buffered; one wait+sync per tile; bias read
// from smem (288B row stride -> conflict-free LDS.64).
#define ASTG 53248
__global__ __launch_bounds__(256, 2) void attn_h(
    const __half* __restrict__ Q, const __half* __restrict__ Kpk,
    const __half* __restrict__ Vpk, const float* __restrict__ bias,
    __half* __restrict__ O16)
{
    extern __shared__ char smc[];
    const int tid = threadIdx.x;
    const int lane = tid & 31;
    const int g = lane >> 2, c = lane & 3;
    const int h = blockIdx.y;
    const int q0 = blockIdx.x * 128;
    const int r0 = 16 * (tid >> 5) + g;
    const unsigned sbase = (unsigned)__cvta_generic_to_shared(smc);
    const uint32_t ONES2 = 0x3C003C00u;

    uint32_t qa[4][4];
    {
        const char* qp0 = (const char*)(Q + (size_t)(q0 + r0) * DM + h * HD);
        const char* qp1 = qp0 + (size_t)8 * DM * 2;
#pragma unroll
        for (int kk = 0; kk < 4; kk++) {
            uint2 t0 = *(const uint2*)(qp0 + kk * 32 + c * 8);
            uint2 t1 = *(const uint2*)(qp1 + kk * 32 + c * 8);
            qa[kk][0] = t0.x; qa[kk][1] = t1.x; qa[kk][2] = t0.y; qa[kk][3] = t1.y;
        }
    }

    float o[8][4];
#pragma unroll
    for (int j = 0; j < 8; j++)
#pragma unroll
        for (int r = 0; r < 4; r++) o[j][r] = 0.f;
    float lacc[4] = {0.f, 0.f, 0.f, 0.f};
    float mr0 = -1e30f, mr1 = -1e30f;

    const __half* kbase = Kpk + (size_t)h * NT * 64;
    const __half* vbase = Vpk + (size_t)h * NT * 64;
    const float*  bbase = bias + ((size_t)h * NT + q0) * NT;

    auto stage = [&](int t) {
        const unsigned s0 = sbase + (t & 1) * ASTG;
        const char* ks = (const char*)(kbase + (size_t)t * 4096);
        const char* vs = (const char*)(vbase + (size_t)t * 4096);
        cpa16(s0 + tid * 16,         ks + tid * 16);
        cpa16(s0 + 4096 + tid * 16,  ks + 4096 + tid * 16);
        cpa16(s0 + 8192 + tid * 16,  vs + tid * 16);
        cpa16(s0 + 12288 + tid * 16, vs + 4096 + tid * 16);
        const float* bsrc = bbase + t * 64;
#pragma unroll
        for (int i = 0; i < 8; i++) {
            int idx = i * 256 + tid;
            int row = idx >> 4, cc = idx & 15;
            cpa16(s0 + 16384 + row * 288 + cc * 16,
                  bsrc + (size_t)row * NT + cc * 4);
        }
        asm volatile("cp.async.commit_group;" ::: "memory");
    };

    stage(0);
    const int swz = (g & 1) << 6;

    for (int t = 0; t < NT / 64; t++) {
        asm volatile("cp.async.wait_group 0;" ::: "memory");
        __syncthreads();
        if (t + 1 < NT / 64) stage(t + 1);

        const char* Ksb = smc + (t & 1) * ASTG;
        const char* Vsb = Ksb + 8192;
        const char* Bsb = Ksb + 16384;

        float s[8][4];
        const char* br0 = Bsb + r0 * 288 + 8 * c;
        const char* br1 = Bsb + (r0 + 8) * 288 + 8 * c;
#pragma unroll
        for (int j = 0; j < 8; j++) {
            float2 b0 = *(const float2*)(br0 + 32 * j);
            float2 b1 = *(const float2*)(br1 + 32 * j);
            s[j][0] = b0.x; s[j][1] = b0.y; s[j][2] = b1.x; s[j][3] = b1.y;
        }
#pragma unroll
        for (int kkp = 0; kkp < 2; kkp++) {
#pragma unroll
            for (int j = 0; j < 8; j++) {
                uint4 kb = *(const uint4*)(Ksb + (8 * j + g) * 128 + c * 16 + ((kkp << 6) ^ swz));
                mma16(s[j], qa[2 * kkp][0], qa[2 * kkp][1], qa[2 * kkp][2], qa[2 * kkp][3], kb.x, kb.y);
                mma16(s[j], qa[2 * kkp + 1][0], qa[2 * kkp + 1][1], qa[2 * kkp + 1][2], qa[2 * kkp + 1][3], kb.z, kb.w);
            }
        }

        float rm0 = -1e30f, rm1 = -1e30f;
#pragma unroll
        for (int j = 0; j < 8; j++) {
            rm0 = fmaxf(rm0, fmaxf(s[j][0], s[j][1]));
            rm1 = fmaxf(rm1, fmaxf(s[j][2], s[j][3]));
        }
        rm0 = fmaxf(rm0, __shfl_xor_sync(0xffffffffu, rm0, 1));
        rm0 = fmaxf(rm0, __shfl_xor_sync(0xffffffffu, rm0, 2));
        rm1 = fmaxf(rm1, __shfl_xor_sync(0xffffffffu, rm1, 1));
        rm1 = fmaxf(rm1, __shfl_xor_sync(0xffffffffu, rm1, 2));

        if (__any_sync(0xffffffffu, (rm0 > mr0) || (rm1 > mr1))) {
            float mn0 = fmaxf(mr0, rm0), mn1 = fmaxf(mr1, rm1);
            float corr0 = fexp(mr0 - mn0), corr1 = fexp(mr1 - mn1);
            mr0 = mn0; mr1 = mn1;
            lacc[0] *= corr0; lacc[1] *= corr0;
            lacc[2] *= corr1; lacc[3] *= corr1;
#pragma unroll
            for (int j = 0; j < 8; j++) {
                o[j][0] *= corr0; o[j][1] *= corr0;
                o[j][2] *= corr1; o[j][3] *= corr1;
            }
        }

        const float mlog0 = mr0 * LOG2E, mlog1 = mr1 * LOG2E;
        uint32_t pf[8][2];
#pragma unroll
        for (int j = 0; j < 8; j++) {
            float y00 = fmaf(s[j][0], LOG2E, -mlog0);
            float y01 = fmaf(s[j][1], LOG2E, -mlog0);
            float y10 = fmaf(s[j][2], LOG2E, -mlog1);
            float y11 = fmaf(s[j][3], LOG2E, -mlog1);
            pf[j][0] = ex2h2(h2u(y00, y01));
            pf[j][1] = ex2h2(h2u(y10, y11));
        }

#pragma unroll
        for (int tkp = 0; tkp < 2; tkp++) {
            uint32_t a00 = pf[4 * tkp + 0][0], a01 = pf[4 * tkp + 0][1];
            uint32_t a02 = pf[4 * tkp + 1][0], a03 = pf[4 * tkp + 1][1];
            uint32_t a10 = pf[4 * tkp + 2][0], a11 = pf[4 * tkp + 2][1];
            uint32_t a12 = pf[4 * tkp + 3][0], a13 = pf[4 * tkp + 3][1];
            mma16(lacc, a00, a01, a02, a03, ONES2, ONES2);
            mma16(lacc, a10, a11, a12, a13, ONES2, ONES2);
#pragma unroll
            for (int j = 0; j < 8; j++) {
                uint4 vb = *(const uint4*)(Vsb + (8 * j + g) * 128 + c * 16 + ((tkp << 6) ^ swz));
                mma16(o[j], a00, a01, a02, a03, vb.x, vb.y);
                mma16(o[j], a10, a11, a12, a13, vb.z, vb.w);
            }
        }
    }

    float inv0 = 1.0f / lacc[0], inv1 = 1.0f / lacc[2];
    const int grow0 = q0 + r0;
#pragma unroll
    for (int j = 0; j < 8; j++) {
        int col = h * HD + 8 * j + 2 * c;
        size_t p = (size_t)grow0 * DM + (col & ~15) + ppos(col & 15);
        *(uint32_t*)&O16[p]                  = h2u(o[j][0] * inv0, o[j][1] * inv0);
        *(uint32_t*)&O16[p + (size_t)8 * DM] = h2u(o[j][2] * inv1, o[j][3] * inv1);
    }
}

// ---------------- warp-per-row residual + LayerNorm -------------------------
template <bool PACK>
__global__ __launch_bounds__(256) void add_ln(
    const float* __restrict__ A, const float* __restrict__ B,
    const float* __restrict__ g, const float* __restrict__ be,
    float* __restrict__ out, __half* __restrict__ out16)
{
    const int row = blockIdx.x * 8 + (threadIdx.x >> 5);
    const int lane = threadIdx.x & 31;
    const float* ap = A + (size_t)row * DM;
    const float* bp = B + (size_t)row * DM;

    float4 v[4];
    float s = 0.f;
#pragma unroll
    for (int i = 0; i < 4; i++) {
        int col = (i * 32 + lane) * 4;
        float4 a = *(const float4*)(ap + col);
        float4 b = *(const float4*)(bp + col);
        v[i] = make_float4(a.x + b.x, a.y + b.y, a.z + b.z, a.w + b.w);
        s += v[i].x + v[i].y + v[i].z + v[i].w;
    }
#pragma unroll
    for (int off = 16; off; off >>= 1) s += __shfl_xor_sync(0xffffffffu, s, off);
    float mu = s * (1.f / DM);

    float sq = 0.f;
#pragma unroll
    for (int i = 0; i < 4; i++) {
        v[i].x -= mu; v[i].y -= mu; v[i].z -= mu; v[i].w -= mu;
        sq += v[i].x * v[i].x + v[i].y * v[i].y + v[i].z * v[i].z + v[i].w * v[i].w;
    }
#pragma unroll
    for (int off = 16; off; off >>= 1) sq += __shfl_xor_sync(0xffffffffu, sq, off);
    float inv = rsqrtf(sq * (1.f / DM) + 1e-5f);

#pragma unroll
    for (int i = 0; i < 4; i++) {
        int col = (i * 32 + lane) * 4;
        float4 gg = *(const float4*)(g + col);
        float4 bb = *(const float4*)(be + col);
        float4 r;
        r.x = v[i].x * inv * gg.x + bb.x;
        r.y = v[i].y * inv * gg.y + bb.y;
        r.z = v[i].z * inv * gg.z + bb.z;
        r.w = v[i].w * inv * gg.w + bb.w;
        *(float4*)(out + (size_t)row * DM + col) = r;
        if (PACK) {
            size_t base = (size_t)row * DM + (col & ~15);
            *(uint32_t*)&out16[base + ppos(col & 15)]       = h2u(r.x, r.y);
            *(uint32_t*)&out16[base + ppos((col + 2) & 15)] = h2u(r.z, r.w);
        }
    }
}

// ---------------- launch ----------------------------------------------------
extern "C" void kernel_launch(void* const* d_in, const int* in_sizes, int n_in,
                              void* d_out, int out_size)
{
    const float* x    = (const float*)d_in[0];
    const float* bias = (const float*)d_in[1];
    const float* Wq = (const float*)d_in[2];  const float* bq = (const float*)d_in[3];
    const float* Wk = (const float*)d_in[4];  const float* bk = (const float*)d_in[5];
    const float* Wv = (const float*)d_in[6];  const float* bv = (const float*)d_in[7];
    const float* Wo = (const float*)d_in[8];  const float* bo = (const float*)d_in[9];
    const float* g1 = (const float*)d_in[10]; const float* b1 = (const float*)d_in[11];
    const float* g2 = (const float*)d_in[12]; const float* b2 = (const float*)d_in[13];
    const float* W1 = (const float*)d_in[14]; const float* c1 = (const float*)d_in[15];
    const float* W2 = (const float*)d_in[16]; const float* c2 = (const float*)d_in[17];
    float* out = (float*)d_out;

    __half *Qp, *Kp, *Vp, *x16p, *attn16p, *x116p, *hid16p;
    __half *WqT, *WkT, *WvT, *WoT, *W1T, *W2T;
    float *tmpp, *x1p;
    cudaGetSymbolAddress((void**)&Qp,     g_Q);
    cudaGetSymbolAddress((void**)&Kp,     g_K);
    cudaGetSymbolAddress((void**)&Vp,     g_V);
    cudaGetSymbolAddress((void**)&x16p,   g_x16);
    cudaGetSymbolAddress((void**)&attn16p, g_attn16);
    cudaGetSymbolAddress((void**)&x116p,  g_x116);
    cudaGetSymbolAddress((void**)&hid16p, g_hid16);
    cudaGetSymbolAddress((void**)&tmpp,   g_tmp);
    cudaGetSymbolAddress((void**)&x1p,    g_x1);
    cudaGetSymbolAddress((void**)&WqT,    g_WqT);
    cudaGetSymbolAddress((void**)&WkT,    g_WkT);
    cudaGetSymbolAddress((void**)&WvT,    g_WvT);
    cudaGetSymbolAddress((void**)&WoT,    g_WoT);
    cudaGetSymbolAddress((void**)&W1T,    g_W1T);
    cudaGetSymbolAddress((void**)&W2T,    g_W2T);

    const int ATTN_SMEM = 2 * ASTG;   // 106496
    cudaFuncSetAttribute(attn_h, cudaFuncAttributeMaxDynamicSharedMemorySize, ATTN_SMEM);

    pack_x<<<NT * DM / 16 / 256, 256>>>(x, x16p);
    transpose_all<<<dim3(DFF / 32, DFF / 32, 6), 256>>>(
        Wq, Wk, Wv, Wo, W1, W2, WqT, WkT, WvT, WoT, W1T, W2T);

    dim3 blk(256);
    qkv16<<<dim3(DM / 128, NT / 128, 3), blk>>>(
        x16p, WqT, bq, Qp, WkT, bk, Kp, WvT, bv, Vp);

    attn_h<<<dim3(NT / 128, NH), blk, ATTN_SMEM>>>(Qp, Kp, Vp, bias, attn16p);

    gemm16<0><<<dim3(DM / 128, NT / 128), blk>>>(attn16p, WoT, bo, tmpp, DM, DM);
    add_ln<true><<<NT / 8, 256>>>(x, tmpp, g1, b1, x1p, x116p);

    gemm16<1><<<dim3(DFF / 128, NT / 128), blk>>>(x116p, W1T, c1, hid16p, DFF, DM);
    gemm16<0><<<dim3(DM / 128, NT / 128), blk>>>(hid16p, W2T, c2, tmpp, DM, DFF);
    add_ln<false><<<NT / 8, 256>>>(x1p, tmpp, g2, b2, out, nullptr);
}

// round 13
// speedup vs baseline: 1.0445x; 1.0445x over previous
#include <cuda_runtime.h>
#include <cuda_fp16.h>
#include <math.h>
#include <stdint.h>

#define NT  4096
#define DM  512
#define NH  8
#define HD  64
#define DFF 1024

// ---------------- scratch (static device globals; no allocations) ----------
__device__ __half g_Q[NT * DM];      // fp16, 0.125-prescaled, pk16-packed
__device__ __half g_K[NT * DM];      // fp16, tile-contiguous packed (khalf_idx)
__device__ __half g_V[NT * DM];      // fp16, tile-contiguous packed (vhalf_idx)
__device__ __half g_x16[NT * DM];    // x packed fp16 (QKV GEMM A operand)
__device__ __half g_attn16[NT * DM]; // attention out packed fp16 (Wo A operand)
__device__ __half g_x116[NT * DM];   // LN1 out packed fp16 (W1 A operand)
__device__ __half g_hid16[NT * DFF]; // FF1 out packed fp16 (W2 A operand)
__device__ float  g_tmp[NT * DM];
__device__ float  g_x1[NT * DM];
// transposed fp16 weights, pk16-packed along k (B operands)
__device__ __half g_WqT[DM * DM];
__device__ __half g_WkT[DM * DM];
__device__ __half g_WvT[DM * DM];
__device__ __half g_WoT[DM * DM];
__device__ __half g_W1T[DFF * DM];
__device__ __half g_W2T[DM * DFF];

#define LOG2E 1.4426950408889634f

// ---------------- helpers ---------------------------------------------------
__host__ __device__ __forceinline__ int ppos(int r) {
    return ((r & 7) >> 1) * 4 + ((r >> 3) & 1) * 2 + (r & 1);
}

__device__ __forceinline__ size_t khalf_idx(int h, int tok, int dim) {
    int tl = tok & 63;
    int r = dim & 15;
    int c = (r >> 1) & 3, q = ((r >> 3) & 1) * 2 + (r & 1);
    int kkl = (dim >> 4) & 1, kkp = (dim >> 5) & 1;
    return (size_t)h * NT * 64 + (size_t)(tok >> 6) * 4096
         + tl * 64 + ((kkp ^ (tl & 1)) << 5) + c * 8 + kkl * 4 + q;
}
__device__ __forceinline__ size_t vhalf_idx(int h, int tok, int n) {
    int r = tok & 15;
    int c = (r >> 1) & 3, q = ((r >> 3) & 1) * 2 + (r & 1);
    int tkl = (tok >> 4) & 1, tkp = (tok >> 5) & 1;
    return (size_t)h * NT * 64 + (size_t)(tok >> 6) * 4096
         + n * 64 + ((tkp ^ (n & 1)) << 5) + c * 8 + tkl * 4 + q;
}

__device__ __forceinline__ uint32_t h2u(float lo, float hi) {
    uint32_t r;
    asm("cvt.rn.f16x2.f32 %0, %1, %2;" : "=r"(r) : "f"(hi), "f"(lo));
    return r;
}

__device__ __forceinline__ uint32_t ex2h2(uint32_t y) {
    uint32_t r;
    asm("ex2.approx.f16x2 %0, %1;" : "=r"(r) : "r"(y));
    return r;
}

__device__ __forceinline__ void mma16(float d[4],
                                      uint32_t a0, uint32_t a1, uint32_t a2, uint32_t a3,
                                      uint32_t b0, uint32_t b1) {
    asm("mma.sync.aligned.m16n8k16.row.col.f32.f16.f16.f32 "
        "{%0,%1,%2,%3}, {%4,%5,%6,%7}, {%8,%9}, {%0,%1,%2,%3};"
        : "+f"(d[0]), "+f"(d[1]), "+f"(d[2]), "+f"(d[3])
        : "r"(a0), "r"(a1), "r"(a2), "r"(a3), "r"(b0), "r"(b1));
}

__device__ __forceinline__ void cpa16(unsigned dst, const void* src) {
    asm volatile("cp.async.cg.shared.global [%0], [%1], 16;" :: "r"(dst), "l"(src));
}

__device__ __forceinline__ float fexp(float x) {
    float r;
    float y = x * LOG2E;
    asm("ex2.approx.f32 %0, %1;" : "=f"(r) : "f"(y));
    return r;
}

// ==================== fp16 GEMM, all-cp.async, 64x128 tile, 3-stage ========
template <int MODE>   // 0: fp32 out + bias; 1: bias + relu -> fp16 pk16 out
__global__ __launch_bounds__(256) void gemm16(
    const __half* __restrict__ A16, const __half* __restrict__ Bt,
    const float* __restrict__ bias, void* __restrict__ Cout, int N, int K)
{
    __shared__ __align__(16) char smem[3 * 12288];
    const int tid = threadIdx.x;
    const int wid = tid >> 5, lane = tid & 31;
    const int g = lane >> 2, c = lane & 3;
    const int wm = (wid >> 2) * 32, wn = (wid & 3) * 32;
    const int m0 = blockIdx.y * 64, n0 = blockIdx.x * 128;
    const unsigned sb = (unsigned)__cvta_generic_to_shared(smem);

    float acc[2][4][4];
#pragma unroll
    for (int t = 0; t < 2; t++)
#pragma unroll
        for (int j = 0; j < 4; j++)
#pragma unroll
            for (int r = 0; r < 4; r++) acc[t][j][r] = 0.f;

    const int arow = tid >> 2, apart = tid & 3;
    const unsigned adst = arow * 64 +
        (((apart >> 1) ^ ((arow >> 1) & 1)) << 5) + (apart & 1) * 16;

    auto stage = [&](int kb, int st) {
        unsigned s0 = sb + st * 12288;
        cpa16(s0 + adst, A16 + (size_t)(m0 + arow) * K + kb * 32 + apart * 8);
#pragma unroll
        for (int i = 0; i < 2; i++) {
            int idx = i * 256 + tid;
            int n = idx >> 2, sub = idx & 3;
            int kk = sub >> 1, part = sub & 1;
            cpa16(s0 + 4096 + kk * 4096 + n * 32 + part * 16,
                  Bt + (size_t)(n0 + n) * K + kb * 32 + kk * 16 + part * 8);
        }
        asm volatile("cp.async.commit_group;" ::: "memory");
    };

    const int nk = K >> 5;
    stage(0, 0);
    stage(1, 1);
    const int aswz = (g >> 1) & 1;

    for (int kb = 0; kb < nk; kb++) {
        if (kb + 1 < nk) {
            asm volatile("cp.async.wait_group 1;" ::: "memory");
        } else {
            asm volatile("cp.async.wait_group 0;" ::: "memory");
        }
        __syncthreads();
        if (kb + 2 < nk) stage(kb + 2, (kb + 2) % 3);

        const char* aB = smem + (kb % 3) * 12288;
        const char* bB = aB + 4096;
#pragma unroll
        for (int kk = 0; kk < 2; kk++) {
            const int ko = ((kk ^ aswz) << 5) + c * 8;
            uint32_t af[2][4];
#pragma unroll
            for (int t = 0; t < 2; t++) {
                uint2 r0 = *(const uint2*)(aB + (wm + 16 * t + g) * 64 + ko);
                uint2 r1 = *(const uint2*)(aB + (wm + 16 * t + g + 8) * 64 + ko);
                af[t][0] = r0.x; af[t][1] = r1.x; af[t][2] = r0.y; af[t][3] = r1.y;
            }
#pragma unroll
            for (int j = 0; j < 4; j++) {
                uint2 bv = *(const uint2*)(bB + kk * 4096 + (wn + 8 * j + g) * 32 + c * 8);
#pragma unroll
                for (int t = 0; t < 2; t++)
                    mma16(acc[t][j], af[t][0], af[t][1], af[t][2], af[t][3], bv.x, bv.y);
            }
        }
        __syncthreads();
    }

#pragma unroll
    for (int t = 0; t < 2; t++) {
        int row0 = m0 + wm + 16 * t + g;
#pragma unroll
        for (int j = 0; j < 4; j++) {
            int col = n0 + wn + 8 * j + 2 * c;
            float2 bv = *(const float2*)&bias[col];
            float v00 = acc[t][j][0] + bv.x, v01 = acc[t][j][1] + bv.y;
            float v10 = acc[t][j][2] + bv.x, v11 = acc[t][j][3] + bv.y;
            if (MODE == 0) {
                float* C = (float*)Cout;
                *(float2*)&C[(size_t)row0 * N + col]       = make_float2(v00, v01);
                *(float2*)&C[(size_t)(row0 + 8) * N + col] = make_float2(v10, v11);
            } else {
                v00 = fmaxf(v00, 0.f); v01 = fmaxf(v01, 0.f);
                v10 = fmaxf(v10, 0.f); v11 = fmaxf(v11, 0.f);
                __half* C = (__half*)Cout;
                size_t p = (size_t)row0 * N + (col & ~15) + ppos(col & 15);
                *(uint32_t*)&C[p]                 = h2u(v00, v01);
                *(uint32_t*)&C[p + (size_t)8 * N] = h2u(v10, v11);
            }
        }
    }
}

// ---------------- fused QKV GEMM (A fp16), z selects projection -------------
__global__ __launch_bounds__(256) void qkv16(
    const __half* __restrict__ x16,
    const __half* __restrict__ WqT, const float* __restrict__ bq, __half* __restrict__ Qo,
    const __half* __restrict__ WkT, const float* __restrict__ bk, __half* __restrict__ Ko,
    const __half* __restrict__ WvT, const float* __restrict__ bv, __half* __restrict__ Vo)
{
    __shared__ __align__(16) char smem[3 * 12288];
    const int z = blockIdx.z;
    const __half* Bt   = (z == 0) ? WqT : (z == 1) ? WkT : WvT;
    const float*  bias = (z == 0) ? bq  : (z == 1) ? bk  : bv;

    const int tid = threadIdx.x;
    const int wid = tid >> 5, lane = tid & 31;
    const int g = lane >> 2, c = lane & 3;
    const int wm = (wid >> 2) * 32, wn = (wid & 3) * 32;
    const int m0 = blockIdx.y * 64, n0 = blockIdx.x * 128;
    const unsigned sb = (unsigned)__cvta_generic_to_shared(smem);

    float acc[2][4][4];
#pragma unroll
    for (int t = 0; t < 2; t++)
#pragma unroll
        for (int j = 0; j < 4; j++)
#pragma unroll
            for (int r = 0; r < 4; r++) acc[t][j][r] = 0.f;

    const int arow = tid >> 2, apart = tid & 3;
    const unsigned adst = arow * 64 +
        (((apart >> 1) ^ ((arow >> 1) & 1)) << 5) + (apart & 1) * 16;

    auto stage = [&](int kb, int st) {
        unsigned s0 = sb + st * 12288;
        cpa16(s0 + adst, x16 + (size_t)(m0 + arow) * DM + kb * 32 + apart * 8);
#pragma unroll
        for (int i = 0; i < 2; i++) {
            int idx = i * 256 + tid;
            int n = idx >> 2, sub = idx & 3;
            int kk = sub >> 1, part = sub & 1;
            cpa16(s0 + 4096 + kk * 4096 + n * 32 + part * 16,
                  Bt + (size_t)(n0 + n) * DM + kb * 32 + kk * 16 + part * 8);
        }
        asm volatile("cp.async.commit_group;" ::: "memory");
    };

    const int nk = DM >> 5;
    stage(0, 0);
    stage(1, 1);
    const int aswz = (g >> 1) & 1;

    for (int kb = 0; kb < nk; kb++) {
        if (kb + 1 < nk) {
            asm volatile("cp.async.wait_group 1;" ::: "memory");
        } else {
            asm volatile("cp.async.wait_group 0;" ::: "memory");
        }
        __syncthreads();
        if (kb + 2 < nk) stage(kb + 2, (kb + 2) % 3);

        const char* aB = smem + (kb % 3) * 12288;
        const char* bB = aB + 4096;
#pragma unroll
        for (int kk = 0; kk < 2; kk++) {
            const int ko = ((kk ^ aswz) << 5) + c * 8;
            uint32_t af[2][4];
#pragma unroll
            for (int t = 0; t < 2; t++) {
                uint2 r0 = *(const uint2*)(aB + (wm + 16 * t + g) * 64 + ko);
                uint2 r1 = *(const uint2*)(aB + (wm + 16 * t + g + 8) * 64 + ko);
                af[t][0] = r0.x; af[t][1] = r1.x; af[t][2] = r0.y; af[t][3] = r1.y;
            }
#pragma unroll
            for (int j = 0; j < 4; j++) {
                uint2 bv2 = *(const uint2*)(bB + kk * 4096 + (wn + 8 * j + g) * 32 + c * 8);
#pragma unroll
                for (int t = 0; t < 2; t++)
                    mma16(acc[t][j], af[t][0], af[t][1], af[t][2], af[t][3], bv2.x, bv2.y);
            }
        }
        __syncthreads();
    }

#pragma unroll
    for (int t = 0; t < 2; t++) {
        int row0 = m0 + wm + 16 * t + g;
#pragma unroll
        for (int j = 0; j < 4; j++) {
            int col = n0 + wn + 8 * j + 2 * c;
            float2 bvv = *(const float2*)&bias[col];
            float v00 = acc[t][j][0] + bvv.x, v01 = acc[t][j][1] + bvv.y;
            float v10 = acc[t][j][2] + bvv.x, v11 = acc[t][j][3] + bvv.y;
            if (z == 0) {
                size_t p0 = (size_t)row0 * DM + (col & ~15) + ppos(col & 15);
                *(uint32_t*)&Qo[p0]                   = h2u(v00 * 0.125f, v01 * 0.125f);
                *(uint32_t*)&Qo[p0 + (size_t)8 * DM]  = h2u(v10 * 0.125f, v11 * 0.125f);
            } else if (z == 1) {
                int h = col >> 6, dl = col & 63;
                *(uint32_t*)&Ko[khalf_idx(h, row0,     dl)] = h2u(v00, v01);
                *(uint32_t*)&Ko[khalf_idx(h, row0 + 8, dl)] = h2u(v10, v11);
            } else {
                int h = col >> 6, dl = col & 63;
                Vo[vhalf_idx(h, row0,     dl)]     = __float2half_rn(v00);
                Vo[vhalf_idx(h, row0,     dl + 1)] = __float2half_rn(v01);
                Vo[vhalf_idx(h, row0 + 8, dl)]     = __float2half_rn(v10);
                Vo[vhalf_idx(h, row0 + 8, dl + 1)] = __float2half_rn(v11);
            }
        }
    }
}

// ---------------- pack x: fp32 [NT][DM] -> fp16 pk16 ------------------------
__global__ void __launch_bounds__(256) pack_x(
    const float* __restrict__ x, __half* __restrict__ o)
{
    int i = blockIdx.x * 256 + threadIdx.x;
    int row = i >> 5, grp = i & 31;
    const float* src = x + (size_t)row * DM + grp * 16;
    uint32_t u[8];
#pragma unroll
    for (int q = 0; q < 4; q++) {
        float4 v = *(const float4*)(src + q * 4);
        int d = q * 4;
        u[ppos(d) >> 1]     = h2u(v.x, v.y);
        u[ppos(d + 2) >> 1] = h2u(v.z, v.w);
    }
    __half* dst = o + (size_t)row * DM + grp * 16;
    *(uint4*)dst       = make_uint4(u[0], u[1], u[2], u[3]);
    *(uint4*)(dst + 8) = make_uint4(u[4], u[5], u[6], u[7]);
}

// ---------------- fused weight transpose: ONE launch for all 6 weights ------
__global__ void __launch_bounds__(256) transpose_all(
    const float* __restrict__ Wq, const float* __restrict__ Wk,
    const float* __restrict__ Wv, const float* __restrict__ Wo,
    const float* __restrict__ W1, const float* __restrict__ W2,
    __half* __restrict__ WqT, __half* __restrict__ WkT,
    __half* __restrict__ WvT, __half* __restrict__ WoT,
    __half* __restrict__ W1T, __half* __restrict__ W2T)
{
    __shared__ float t[32][33];
    const int z = blockIdx.z;
    const float* in; __half* outp; int K, N;
    switch (z) {
        case 0:  in = Wq; outp = WqT; K = DM;  N = DM;  break;
        case 1:  in = Wk; outp = WkT; K = DM;  N = DM;  break;
        case 2:  in = Wv; outp = WvT; K = DM;  N = DM;  break;
        case 3:  in = Wo; outp = WoT; K = DM;  N = DM;  break;
        case 4:  in = W1; outp = W1T; K = DM;  N = DFF; break;
        default: in = W2; outp = W2T; K = DFF; N = DM;  break;
    }
    const int n0 = blockIdx.x * 32, k0 = blockIdx.y * 32;
    if (n0 >= N || k0 >= K) return;
    const int tx = threadIdx.x & 31, ty = threadIdx.x >> 5;
#pragma unroll
    for (int i = 0; i < 4; i++)
        t[ty + 8 * i][tx] = in[(size_t)(k0 + ty + 8 * i) * N + n0 + tx];
    __syncthreads();
    if (tx < 16) {
#pragma unroll
        for (int i = 0; i < 4; i++) {
            int n = ty + 8 * i;
            int kl = 2 * tx;
            int pos = (kl & ~15) + ppos(kl & 15);
            *(uint32_t*)&outp[(size_t)(n0 + n) * K + k0 + pos] =
                h2u(t[kl][n], t[kl + 1][n]);
        }
    }
}

// ---------------- fp16 tensor-core flash attention --------------------------
// Split commit groups: KV (16KB) then bias (36.9KB) per tile. S-mma waits
// only on KV; bias tail overlaps the S-mma chain. Two barriers per tile.
#define ASTG 53248
#define NTILES (NT / 64)
__global__ __launch_bounds__(256, 2) void attn_h(
    const __half* __restrict__ Q, const __half* __restrict__ Kpk,
    const __half* __restrict__ Vpk, const float* __restrict__ bias,
    __half* __restrict__ O16)
{
    extern __shared__ char smc[];
    const int tid = threadIdx.x;
    const int lane = tid & 31;
    const int g = lane >> 2, c = lane & 3;
    const int h = blockIdx.y;
    const int q0 = blockIdx.x * 128;
    const int r0 = 16 * (tid >> 5) + g;
    const unsigned sbase = (unsigned)__cvta_generic_to_shared(smc);
    const uint32_t ONES2 = 0x3C003C00u;

    uint32_t qa[4][4];
    {
        const char* qp0 = (const char*)(Q + (size_t)(q0 + r0) * DM + h * HD);
        const char* qp1 = qp0 + (size_t)8 * DM * 2;
#pragma unroll
        for (int kk = 0; kk < 4; kk++) {
            uint2 t0 = *(const uint2*)(qp0 + kk * 32 + c * 8);
            uint2 t1 = *(const uint2*)(qp1 + kk * 32 + c * 8);
            qa[kk][0] = t0.x; qa[kk][1] = t1.x; qa[kk][2] = t0.y; qa[kk][3] = t1.y;
        }
    }

    float o[8][4];
#pragma unroll
    for (int j = 0; j < 8; j++)
#pragma unroll
        for (int r = 0; r < 4; r++) o[j][r] = 0.f;
    float lacc[4] = {0.f, 0.f, 0.f, 0.f};
    float mr0 = -1e30f, mr1 = -1e30f;

    const __half* kbase = Kpk + (size_t)h * NT * 64;
    const __half* vbase = Vpk + (size_t)h * NT * 64;
    const float*  bbase = bias + ((size_t)h * NT + q0) * NT;

    auto stage_kv = [&](int t) {
        const unsigned s0 = sbase + (t & 1) * ASTG;
        const char* ks = (const char*)(kbase + (size_t)t * 4096);
        const char* vs = (const char*)(vbase + (size_t)t * 4096);
        cpa16(s0 + tid * 16,         ks + tid * 16);
        cpa16(s0 + 4096 + tid * 16,  ks + 4096 + tid * 16);
        cpa16(s0 + 8192 + tid * 16,  vs + tid * 16);
        cpa16(s0 + 12288 + tid * 16, vs + 4096 + tid * 16);
        asm volatile("cp.async.commit_group;" ::: "memory");
    };
    auto stage_bias = [&](int t) {
        const unsigned s0 = sbase + (t & 1) * ASTG;
        const float* bsrc = bbase + t * 64;
#pragma unroll
        for (int i = 0; i < 8; i++) {
            int idx = i * 256 + tid;
            int row = idx >> 4, cc = idx & 15;
            cpa16(s0 + 16384 + row * 288 + cc * 16,
                  bsrc + (size_t)row * NT + cc * 4);
        }
        asm volatile("cp.async.commit_group;" ::: "memory");
    };

    stage_kv(0);
    stage_bias(0);
    const int swz = (g & 1) << 6;

    for (int t = 0; t < NTILES; t++) {
        // KV(t) complete (bias(t) may still be in flight)
        asm volatile("cp.async.wait_group 1;" ::: "memory");
        __syncthreads();          // KV(t) visible; buffers of t-1 free
        if (t + 1 < NTILES) {
            stage_kv(t + 1);      // pending: bias(t), kv(t+1), bias(t+1)
            stage_bias(t + 1);
        }

        const char* Ksb = smc + (t & 1) * ASTG;
        const char* Vsb = Ksb + 8192;
        const char* Bsb = Ksb + 16384;

        // ---- S = Q@K^T (no bias dependency -> overlaps bias(t) tail) -------
        float s[8][4];
#pragma unroll
        for (int j = 0; j < 8; j++) {
            s[j][0] = 0.f; s[j][1] = 0.f; s[j][2] = 0.f; s[j][3] = 0.f;
        }
#pragma unroll
        for (int kkp = 0; kkp < 2; kkp++) {
#pragma unroll
            for (int j = 0; j < 8; j++) {
                uint4 kb = *(const uint4*)(Ksb + (8 * j + g) * 128 + c * 16 + ((kkp << 6) ^ swz));
                mma16(s[j], qa[2 * kkp][0], qa[2 * kkp][1], qa[2 * kkp][2], qa[2 * kkp][3], kb.x, kb.y);
                mma16(s[j], qa[2 * kkp + 1][0], qa[2 * kkp + 1][1], qa[2 * kkp + 1][2], qa[2 * kkp + 1][3], kb.z, kb.w);
            }
        }

        // bias(t) complete + visible
        if (t + 1 < NTILES) {
            asm volatile("cp.async.wait_group 2;" ::: "memory");
        } else {
            asm volatile("cp.async.wait_group 0;" ::: "memory");
        }
        __syncthreads();

        const char* br0 = Bsb + r0 * 288 + 8 * c;
        const char* br1 = Bsb + (r0 + 8) * 288 + 8 * c;
#pragma unroll
        for (int j = 0; j < 8; j++) {
            float2 b0 = *(const float2*)(br0 + 32 * j);
            float2 b1 = *(const float2*)(br1 + 32 * j);
            s[j][0] += b0.x; s[j][1] += b0.y; s[j][2] += b1.x; s[j][3] += b1.y;
        }

        // ---- row max (c-group reduce) ---------------------------------------
        float rm0 = -1e30f, rm1 = -1e30f;
#pragma unroll
        for (int j = 0; j < 8; j++) {
            rm0 = fmaxf(rm0, fmaxf(s[j][0], s[j][1]));
            rm1 = fmaxf(rm1, fmaxf(s[j][2], s[j][3]));
        }
        rm0 = fmaxf(rm0, __shfl_xor_sync(0xffffffffu, rm0, 1));
        rm0 = fmaxf(rm0, __shfl_xor_sync(0xffffffffu, rm0, 2));
        rm1 = fmaxf(rm1, __shfl_xor_sync(0xffffffffu, rm1, 1));
        rm1 = fmaxf(rm1, __shfl_xor_sync(0xffffffffu, rm1, 2));

        if (__any_sync(0xffffffffu, (rm0 > mr0) || (rm1 > mr1))) {
            float mn0 = fmaxf(mr0, rm0), mn1 = fmaxf(mr1, rm1);
            float corr0 = fexp(mr0 - mn0), corr1 = fexp(mr1 - mn1);
            mr0 = mn0; mr1 = mn1;
            lacc[0] *= corr0; lacc[1] *= corr0;
            lacc[2] *= corr1; lacc[3] *= corr1;
#pragma unroll
            for (int j = 0; j < 8; j++) {
                o[j][0] *= corr0; o[j][1] *= corr0;
                o[j][2] *= corr1; o[j][3] *= corr1;
            }
        }

        // ---- P = exp2(S*log2e - m*log2e) as fp16x2 PV A-fragments ----------
        const float mlog0 = mr0 * LOG2E, mlog1 = mr1 * LOG2E;
        uint32_t pf[8][2];
#pragma unroll
        for (int j = 0; j < 8; j++) {
            float y00 = fmaf(s[j][0], LOG2E, -mlog0);
            float y01 = fmaf(s[j][1], LOG2E, -mlog0);
            float y10 = fmaf(s[j][2], LOG2E, -mlog1);
            float y11 = fmaf(s[j][3], LOG2E, -mlog1);
            pf[j][0] = ex2h2(h2u(y00, y01));
            pf[j][1] = ex2h2(h2u(y10, y11));
        }

        // ---- O += P @ V ; l += P @ ones -------------------------------------
#pragma unroll
        for (int tkp = 0; tkp < 2; tkp++) {
            uint32_t a00 = pf[4 * tkp + 0][0], a01 = pf[4 * tkp + 0][1];
            uint32_t a02 = pf[4 * tkp + 1][0], a03 = pf[4 * tkp + 1][1];
            uint32_t a10 = pf[4 * tkp + 2][0], a11 = pf[4 * tkp + 2][1];
            uint32_t a12 = pf[4 * tkp + 3][0], a13 = pf[4 * tkp + 3][1];
            mma16(lacc, a00, a01, a02, a03, ONES2, ONES2);
            mma16(lacc, a10, a11, a12, a13, ONES2, ONES2);
#pragma unroll
            for (int j = 0; j < 8; j++) {
                uint4 vb = *(const uint4*)(Vsb + (8 * j + g) * 128 + c * 16 + ((tkp << 6) ^ swz));
                mma16(o[j], a00, a01, a02, a03, vb.x, vb.y);
                mma16(o[j], a10, a11, a12, a13, vb.z, vb.w);
            }
        }
    }

    float inv0 = 1.0f / lacc[0], inv1 = 1.0f / lacc[2];
    const int grow0 = q0 + r0;
#pragma unroll
    for (int j = 0; j < 8; j++) {
        int col = h * HD + 8 * j + 2 * c;
        size_t p = (size_t)grow0 * DM + (col & ~15) + ppos(col & 15);
        *(uint32_t*)&O16[p]                  = h2u(o[j][0] * inv0, o[j][1] * inv0);
        *(uint32_t*)&O16[p + (size_t)8 * DM] = h2u(o[j][2] * inv1, o[j][3] * inv1);
    }
}

// ---------------- warp-per-row residual + LayerNorm -------------------------
template <bool PACK>
__global__ __launch_bounds__(256) void add_ln(
    const float* __restrict__ A, const float* __restrict__ B,
    const float* __restrict__ g, const float* __restrict__ be,
    float* __restrict__ out, __half* __restrict__ out16)
{
    const int row = blockIdx.x * 8 + (threadIdx.x >> 5);
    const int lane = threadIdx.x & 31;
    const float* ap = A + (size_t)row * DM;
    const float* bp = B + (size_t)row * DM;

    float4 v[4];
    float s = 0.f;
#pragma unroll
    for (int i = 0; i < 4; i++) {
        int col = (i * 32 + lane) * 4;
        float4 a = *(const float4*)(ap + col);
        float4 b = *(const float4*)(bp + col);
        v[i] = make_float4(a.x + b.x, a.y + b.y, a.z + b.z, a.w + b.w);
        s += v[i].x + v[i].y + v[i].z + v[i].w;
    }
#pragma unroll
    for (int off = 16; off; off >>= 1) s += __shfl_xor_sync(0xffffffffu, s, off);
    float mu = s * (1.f / DM);

    float sq = 0.f;
#pragma unroll
    for (int i = 0; i < 4; i++) {
        v[i].x -= mu; v[i].y -= mu; v[i].z -= mu; v[i].w -= mu;
        sq += v[i].x * v[i].x + v[i].y * v[i].y + v[i].z * v[i].z + v[i].w * v[i].w;
    }
#pragma unroll
    for (int off = 16; off; off >>= 1) sq += __shfl_xor_sync(0xffffffffu, sq, off);
    float inv = rsqrtf(sq * (1.f / DM) + 1e-5f);

#pragma unroll
    for (int i = 0; i < 4; i++) {
        int col = (i * 32 + lane) * 4;
        float4 gg = *(const float4*)(g + col);
        float4 bb = *(const float4*)(be + col);
        float4 r;
        r.x = v[i].x * inv * gg.x + bb.x;
        r.y = v[i].y * inv * gg.y + bb.y;
        r.z = v[i].z * inv * gg.z + bb.z;
        r.w = v[i].w * inv * gg.w + bb.w;
        *(float4*)(out + (size_t)row * DM + col) = r;
        if (PACK) {
            size_t base = (size_t)row * DM + (col & ~15);
            *(uint32_t*)&out16[base + ppos(col & 15)]       = h2u(r.x, r.y);
            *(uint32_t*)&out16[base + ppos((col + 2) & 15)] = h2u(r.z, r.w);
        }
    }
}

// ---------------- launch ----------------------------------------------------
extern "C" void kernel_launch(void* const* d_in, const int* in_sizes, int n_in,
                              void* d_out, int out_size)
{
    const float* x    = (const float*)d_in[0];
    const float* bias = (const float*)d_in[1];
    const float* Wq = (const float*)d_in[2];  const float* bq = (const float*)d_in[3];
    const float* Wk = (const float*)d_in[4];  const float* bk = (const float*)d_in[5];
    const float* Wv = (const float*)d_in[6];  const float* bv = (const float*)d_in[7];
    const float* Wo = (const float*)d_in[8];  const float* bo = (const float*)d_in[9];
    const float* g1 = (const float*)d_in[10]; const float* b1 = (const float*)d_in[11];
    const float* g2 = (const float*)d_in[12]; const float* b2 = (const float*)d_in[13];
    const float* W1 = (const float*)d_in[14]; const float* c1 = (const float*)d_in[15];
    const float* W2 = (const float*)d_in[16]; const float* c2 = (const float*)d_in[17];
    float* out = (float*)d_out;

    __half *Qp, *Kp, *Vp, *x16p, *attn16p, *x116p, *hid16p;
    __half *WqT, *WkT, *WvT, *WoT, *W1T, *W2T;
    float *tmpp, *x1p;
    cudaGetSymbolAddress((void**)&Qp,     g_Q);
    cudaGetSymbolAddress((void**)&Kp,     g_K);
    cudaGetSymbolAddress((void**)&Vp,     g_V);
    cudaGetSymbolAddress((void**)&x16p,   g_x16);
    cudaGetSymbolAddress((void**)&attn16p, g_attn16);
    cudaGetSymbolAddress((void**)&x116p,  g_x116);
    cudaGetSymbolAddress((void**)&hid16p, g_hid16);
    cudaGetSymbolAddress((void**)&tmpp,   g_tmp);
    cudaGetSymbolAddress((void**)&x1p,    g_x1);
    cudaGetSymbolAddress((void**)&WqT,    g_WqT);
    cudaGetSymbolAddress((void**)&WkT,    g_WkT);
    cudaGetSymbolAddress((void**)&WvT,    g_WvT);
    cudaGetSymbolAddress((void**)&WoT,    g_WoT);
    cudaGetSymbolAddress((void**)&W1T,    g_W1T);
    cudaGetSymbolAddress((void**)&W2T,    g_W2T);

    const int ATTN_SMEM = 2 * ASTG;   // 106496
    cudaFuncSetAttribute(attn_h, cudaFuncAttributeMaxDynamicSharedMemorySize, ATTN_SMEM);

    pack_x<<<NT * DM / 16 / 256, 256>>>(x, x16p);
    transpose_all<<<dim3(DFF / 32, DFF / 32, 6), 256>>>(
        Wq, Wk, Wv, Wo, W1, W2, WqT, WkT, WvT, WoT, W1T, W2T);

    dim3 blk(256);
    qkv16<<<dim3(DM / 128, NT / 64, 3), blk>>>(
        x16p, WqT, bq, Qp, WkT, bk, Kp, WvT, bv, Vp);

    attn_h<<<dim3(NT / 128, NH), blk, ATTN_SMEM>>>(Qp, Kp, Vp, bias, attn16p);

    gemm16<0><<<dim3(DM / 128, NT / 64), blk>>>(attn16p, WoT, bo, tmpp, DM, DM);
    add_ln<true><<<NT / 8, 256>>>(x, tmpp, g1, b1, x1p, x116p);

    gemm16<1><<<dim3(DFF / 128, NT / 64), blk>>>(x116p, W1T, c1, hid16p, DFF, DM);
    gemm16<0><<<dim3(DM / 128, NT / 64), blk>>>(hid16p, W2T, c2, tmpp, DM, DFF);
    add_ln<false><<<NT / 8, 256>>>(x1p, tmpp, g2, b2, out, nullptr);
}

// round 14
// speedup vs baseline: 1.0731x; 1.0274x over previous
#include <cuda_runtime.h>
#include <cuda_fp16.h>
#include <math.h>
#include <stdint.h>

#define NT  4096
#define DM  512
#define NH  8
#define HD  64
#define DFF 1024

// ---------------- scratch (static device globals; no allocations) ----------
__device__ __half g_Q[NT * DM];      // fp16, 0.125-prescaled, pk16-packed
__device__ __half g_K[NT * DM];      // fp16, tile-contiguous packed (khalf_idx)
__device__ __half g_V[NT * DM];      // fp16, tile-contiguous packed (vhalf_idx)
__device__ __half g_x16[NT * DM];    // x packed fp16 (QKV GEMM A operand)
__device__ __half g_attn16[NT * DM]; // attention out packed fp16 (Wo A operand)
__device__ __half g_x116[NT * DM];   // LN1 out packed fp16 (W1 A operand)
__device__ __half g_hid16[NT * DFF]; // FF1 out packed fp16 (W2 A operand)
__device__ float  g_tmp[NT * DM];
__device__ float  g_x1[NT * DM];
// transposed fp16 weights, pk16-packed along k (B operands)
__device__ __half g_WqT[DM * DM];
__device__ __half g_WkT[DM * DM];
__device__ __half g_WvT[DM * DM];
__device__ __half g_WoT[DM * DM];
__device__ __half g_W1T[DFF * DM];
__device__ __half g_W2T[DM * DFF];

#define LOG2E 1.4426950408889634f

// ---------------- helpers ---------------------------------------------------
__host__ __device__ __forceinline__ int ppos(int r) {
    return ((r & 7) >> 1) * 4 + ((r >> 3) & 1) * 2 + (r & 1);
}

__device__ __forceinline__ size_t khalf_idx(int h, int tok, int dim) {
    int tl = tok & 63;
    int r = dim & 15;
    int c = (r >> 1) & 3, q = ((r >> 3) & 1) * 2 + (r & 1);
    int kkl = (dim >> 4) & 1, kkp = (dim >> 5) & 1;
    return (size_t)h * NT * 64 + (size_t)(tok >> 6) * 4096
         + tl * 64 + ((kkp ^ (tl & 1)) << 5) + c * 8 + kkl * 4 + q;
}
__device__ __forceinline__ size_t vhalf_idx(int h, int tok, int n) {
    int r = tok & 15;
    int c = (r >> 1) & 3, q = ((r >> 3) & 1) * 2 + (r & 1);
    int tkl = (tok >> 4) & 1, tkp = (tok >> 5) & 1;
    return (size_t)h * NT * 64 + (size_t)(tok >> 6) * 4096
         + n * 64 + ((tkp ^ (n & 1)) << 5) + c * 8 + tkl * 4 + q;
}

__device__ __forceinline__ uint32_t h2u(float lo, float hi) {
    uint32_t r;
    asm("cvt.rn.f16x2.f32 %0, %1, %2;" : "=r"(r) : "f"(hi), "f"(lo));
    return r;
}

__device__ __forceinline__ uint32_t ex2h2(uint32_t y) {
    uint32_t r;
    asm("ex2.approx.f16x2 %0, %1;" : "=r"(r) : "r"(y));
    return r;
}

__device__ __forceinline__ void mma16(float d[4],
                                      uint32_t a0, uint32_t a1, uint32_t a2, uint32_t a3,
                                      uint32_t b0, uint32_t b1) {
    asm("mma.sync.aligned.m16n8k16.row.col.f32.f16.f16.f32 "
        "{%0,%1,%2,%3}, {%4,%5,%6,%7}, {%8,%9}, {%0,%1,%2,%3};"
        : "+f"(d[0]), "+f"(d[1]), "+f"(d[2]), "+f"(d[3])
        : "r"(a0), "r"(a1), "r"(a2), "r"(a3), "r"(b0), "r"(b1));
}

__device__ __forceinline__ void cpa16(unsigned dst, const void* src) {
    asm volatile("cp.async.cg.shared.global [%0], [%1], 16;" :: "r"(dst), "l"(src));
}

__device__ __forceinline__ float fexp(float x) {
    float r;
    float y = x * LOG2E;
    asm("ex2.approx.f32 %0, %1;" : "=f"(r) : "f"(y));
    return r;
}

// ==================== fp16 GEMM, all-cp.async, 64x128 tile, 4-stage ========
// 3 CTAs/SM (reg-capped) + 3 tiles in flight for deep latency cover.
template <int MODE>   // 0: fp32 out + bias; 1: bias + relu -> fp16 pk16 out
__global__ __launch_bounds__(256, 3) void gemm16(
    const __half* __restrict__ A16, const __half* __restrict__ Bt,
    const float* __restrict__ bias, void* __restrict__ Cout, int N, int K)
{
    __shared__ __align__(16) char smem[4 * 12288];
    const int tid = threadIdx.x;
    const int wid = tid >> 5, lane = tid & 31;
    const int g = lane >> 2, c = lane & 3;
    const int wm = (wid >> 2) * 32, wn = (wid & 3) * 32;
    const int m0 = blockIdx.y * 64, n0 = blockIdx.x * 128;
    const unsigned sb = (unsigned)__cvta_generic_to_shared(smem);

    float acc[2][4][4];
#pragma unroll
    for (int t = 0; t < 2; t++)
#pragma unroll
        for (int j = 0; j < 4; j++)
#pragma unroll
            for (int r = 0; r < 4; r++) acc[t][j][r] = 0.f;

    const int arow = tid >> 2, apart = tid & 3;
    const unsigned adst = arow * 64 +
        (((apart >> 1) ^ ((arow >> 1) & 1)) << 5) + (apart & 1) * 16;

    auto stage = [&](int kb, int st) {
        unsigned s0 = sb + st * 12288;
        cpa16(s0 + adst, A16 + (size_t)(m0 + arow) * K + kb * 32 + apart * 8);
#pragma unroll
        for (int i = 0; i < 2; i++) {
            int idx = i * 256 + tid;
            int n = idx >> 2, sub = idx & 3;
            int kk = sub >> 1, part = sub & 1;
            cpa16(s0 + 4096 + kk * 4096 + n * 32 + part * 16,
                  Bt + (size_t)(n0 + n) * K + kb * 32 + kk * 16 + part * 8);
        }
        asm volatile("cp.async.commit_group;" ::: "memory");
    };

    const int nk = K >> 5;
    stage(0, 0);
    stage(1, 1);
    stage(2, 2);
    const int aswz = (g >> 1) & 1;

    for (int kb = 0; kb < nk; kb++) {
        const int rem = nk - 1 - kb;
        if (rem >= 2) {
            asm volatile("cp.async.wait_group 2;" ::: "memory");
        } else if (rem == 1) {
            asm volatile("cp.async.wait_group 1;" ::: "memory");
        } else {
            asm volatile("cp.async.wait_group 0;" ::: "memory");
        }
        __syncthreads();
        if (kb + 3 < nk) stage(kb + 3, (kb + 3) & 3);

        const char* aB = smem + (kb & 3) * 12288;
        const char* bB = aB + 4096;
#pragma unroll
        for (int kk = 0; kk < 2; kk++) {
            const int ko = ((kk ^ aswz) << 5) + c * 8;
            uint32_t af[2][4];
#pragma unroll
            for (int t = 0; t < 2; t++) {
                uint2 r0 = *(const uint2*)(aB + (wm + 16 * t + g) * 64 + ko);
                uint2 r1 = *(const uint2*)(aB + (wm + 16 * t + g + 8) * 64 + ko);
                af[t][0] = r0.x; af[t][1] = r1.x; af[t][2] = r0.y; af[t][3] = r1.y;
            }
#pragma unroll
            for (int j = 0; j < 4; j++) {
                uint2 bv = *(const uint2*)(bB + kk * 4096 + (wn + 8 * j + g) * 32 + c * 8);
#pragma unroll
                for (int t = 0; t < 2; t++)
                    mma16(acc[t][j], af[t][0], af[t][1], af[t][2], af[t][3], bv.x, bv.y);
            }
        }
        __syncthreads();
    }

#pragma unroll
    for (int t = 0; t < 2; t++) {
        int row0 = m0 + wm + 16 * t + g;
#pragma unroll
        for (int j = 0; j < 4; j++) {
            int col = n0 + wn + 8 * j + 2 * c;
            float2 bv = *(const float2*)&bias[col];
            float v00 = acc[t][j][0] + bv.x, v01 = acc[t][j][1] + bv.y;
            float v10 = acc[t][j][2] + bv.x, v11 = acc[t][j][3] + bv.y;
            if (MODE == 0) {
                float* C = (float*)Cout;
                *(float2*)&C[(size_t)row0 * N + col]       = make_float2(v00, v01);
                *(float2*)&C[(size_t)(row0 + 8) * N + col] = make_float2(v10, v11);
            } else {
                v00 = fmaxf(v00, 0.f); v01 = fmaxf(v01, 0.f);
                v10 = fmaxf(v10, 0.f); v11 = fmaxf(v11, 0.f);
                __half* C = (__half*)Cout;
                size_t p = (size_t)row0 * N + (col & ~15) + ppos(col & 15);
                *(uint32_t*)&C[p]                 = h2u(v00, v01);
                *(uint32_t*)&C[p + (size_t)8 * N] = h2u(v10, v11);
            }
        }
    }
}

// ---------------- fused QKV GEMM (A fp16), z selects projection -------------
__global__ __launch_bounds__(256, 3) void qkv16(
    const __half* __restrict__ x16,
    const __half* __restrict__ WqT, const float* __restrict__ bq, __half* __restrict__ Qo,
    const __half* __restrict__ WkT, const float* __restrict__ bk, __half* __restrict__ Ko,
    const __half* __restrict__ WvT, const float* __restrict__ bv, __half* __restrict__ Vo)
{
    __shared__ __align__(16) char smem[4 * 12288];
    const int z = blockIdx.z;
    const __half* Bt   = (z == 0) ? WqT : (z == 1) ? WkT : WvT;
    const float*  bias = (z == 0) ? bq  : (z == 1) ? bk  : bv;

    const int tid = threadIdx.x;
    const int wid = tid >> 5, lane = tid & 31;
    const int g = lane >> 2, c = lane & 3;
    const int wm = (wid >> 2) * 32, wn = (wid & 3) * 32;
    const int m0 = blockIdx.y * 64, n0 = blockIdx.x * 128;
    const unsigned sb = (unsigned)__cvta_generic_to_shared(smem);

    float acc[2][4][4];
#pragma unroll
    for (int t = 0; t < 2; t++)
#pragma unroll
        for (int j = 0; j < 4; j++)
#pragma unroll
            for (int r = 0; r < 4; r++) acc[t][j][r] = 0.f;

    const int arow = tid >> 2, apart = tid & 3;
    const unsigned adst = arow * 64 +
        (((apart >> 1) ^ ((arow >> 1) & 1)) << 5) + (apart & 1) * 16;

    auto stage = [&](int kb, int st) {
        unsigned s0 = sb + st * 12288;
        cpa16(s0 + adst, x16 + (size_t)(m0 + arow) * DM + kb * 32 + apart * 8);
#pragma unroll
        for (int i = 0; i < 2; i++) {
            int idx = i * 256 + tid;
            int n = idx >> 2, sub = idx & 3;
            int kk = sub >> 1, part = sub & 1;
            cpa16(s0 + 4096 + kk * 4096 + n * 32 + part * 16,
                  Bt + (size_t)(n0 + n) * DM + kb * 32 + kk * 16 + part * 8);
        }
        asm volatile("cp.async.commit_group;" ::: "memory");
    };

    const int nk = DM >> 5;
    stage(0, 0);
    stage(1, 1);
    stage(2, 2);
    const int aswz = (g >> 1) & 1;

    for (int kb = 0; kb < nk; kb++) {
        const int rem = nk - 1 - kb;
        if (rem >= 2) {
            asm volatile("cp.async.wait_group 2;" ::: "memory");
        } else if (rem == 1) {
            asm volatile("cp.async.wait_group 1;" ::: "memory");
        } else {
            asm volatile("cp.async.wait_group 0;" ::: "memory");
        }
        __syncthreads();
        if (kb + 3 < nk) stage(kb + 3, (kb + 3) & 3);

        const char* aB = smem + (kb & 3) * 12288;
        const char* bB = aB + 4096;
#pragma unroll
        for (int kk = 0; kk < 2; kk++) {
            const int ko = ((kk ^ aswz) << 5) + c * 8;
            uint32_t af[2][4];
#pragma unroll
            for (int t = 0; t < 2; t++) {
                uint2 r0 = *(const uint2*)(aB + (wm + 16 * t + g) * 64 + ko);
                uint2 r1 = *(const uint2*)(aB + (wm + 16 * t + g + 8) * 64 + ko);
                af[t][0] = r0.x; af[t][1] = r1.x; af[t][2] = r0.y; af[t][3] = r1.y;
            }
#pragma unroll
            for (int j = 0; j < 4; j++) {
                uint2 bv2 = *(const uint2*)(bB + kk * 4096 + (wn + 8 * j + g) * 32 + c * 8);
#pragma unroll
                for (int t = 0; t < 2; t++)
                    mma16(acc[t][j], af[t][0], af[t][1], af[t][2], af[t][3], bv2.x, bv2.y);
            }
        }
        __syncthreads();
    }

#pragma unroll
    for (int t = 0; t < 2; t++) {
        int row0 = m0 + wm + 16 * t + g;
#pragma unroll
        for (int j = 0; j < 4; j++) {
            int col = n0 + wn + 8 * j + 2 * c;
            float2 bvv = *(const float2*)&bias[col];
            float v00 = acc[t][j][0] + bvv.x, v01 = acc[t][j][1] + bvv.y;
            float v10 = acc[t][j][2] + bvv.x, v11 = acc[t][j][3] + bvv.y;
            if (z == 0) {
                size_t p0 = (size_t)row0 * DM + (col & ~15) + ppos(col & 15);
                *(uint32_t*)&Qo[p0]                   = h2u(v00 * 0.125f, v01 * 0.125f);
                *(uint32_t*)&Qo[p0 + (size_t)8 * DM]  = h2u(v10 * 0.125f, v11 * 0.125f);
            } else if (z == 1) {
                int h = col >> 6, dl = col & 63;
                *(uint32_t*)&Ko[khalf_idx(h, row0,     dl)] = h2u(v00, v01);
                *(uint32_t*)&Ko[khalf_idx(h, row0 + 8, dl)] = h2u(v10, v11);
            } else {
                int h = col >> 6, dl = col & 63;
                Vo[vhalf_idx(h, row0,     dl)]     = __float2half_rn(v00);
                Vo[vhalf_idx(h, row0,     dl + 1)] = __float2half_rn(v01);
                Vo[vhalf_idx(h, row0 + 8, dl)]     = __float2half_rn(v10);
                Vo[vhalf_idx(h, row0 + 8, dl + 1)] = __float2half_rn(v11);
            }
        }
    }
}

// ---------------- pack x: fp32 [NT][DM] -> fp16 pk16 ------------------------
__global__ void __launch_bounds__(256) pack_x(
    const float* __restrict__ x, __half* __restrict__ o)
{
    int i = blockIdx.x * 256 + threadIdx.x;
    int row = i >> 5, grp = i & 31;
    const float* src = x + (size_t)row * DM + grp * 16;
    uint32_t u[8];
#pragma unroll
    for (int q = 0; q < 4; q++) {
        float4 v = *(const float4*)(src + q * 4);
        int d = q * 4;
        u[ppos(d) >> 1]     = h2u(v.x, v.y);
        u[ppos(d + 2) >> 1] = h2u(v.z, v.w);
    }
    __half* dst = o + (size_t)row * DM + grp * 16;
    *(uint4*)dst       = make_uint4(u[0], u[1], u[2], u[3]);
    *(uint4*)(dst + 8) = make_uint4(u[4], u[5], u[6], u[7]);
}

// ---------------- fused weight transpose: ONE launch for all 6 weights ------
__global__ void __launch_bounds__(256) transpose_all(
    const float* __restrict__ Wq, const float* __restrict__ Wk,
    const float* __restrict__ Wv, const float* __restrict__ Wo,
    const float* __restrict__ W1, const float* __restrict__ W2,
    __half* __restrict__ WqT, __half* __restrict__ WkT,
    __half* __restrict__ WvT, __half* __restrict__ WoT,
    __half* __restrict__ W1T, __half* __restrict__ W2T)
{
    __shared__ float t[32][33];
    const int z = blockIdx.z;
    const float* in; __half* outp; int K, N;
    switch (z) {
        case 0:  in = Wq; outp = WqT; K = DM;  N = DM;  break;
        case 1:  in = Wk; outp = WkT; K = DM;  N = DM;  break;
        case 2:  in = Wv; outp = WvT; K = DM;  N = DM;  break;
        case 3:  in = Wo; outp = WoT; K = DM;  N = DM;  break;
        case 4:  in = W1; outp = W1T; K = DM;  N = DFF; break;
        default: in = W2; outp = W2T; K = DFF; N = DM;  break;
    }
    const int n0 = blockIdx.x * 32, k0 = blockIdx.y * 32;
    if (n0 >= N || k0 >= K) return;
    const int tx = threadIdx.x & 31, ty = threadIdx.x >> 5;
#pragma unroll
    for (int i = 0; i < 4; i++)
        t[ty + 8 * i][tx] = in[(size_t)(k0 + ty + 8 * i) * N + n0 + tx];
    __syncthreads();
    if (tx < 16) {
#pragma unroll
        for (int i = 0; i < 4; i++) {
            int n = ty + 8 * i;
            int kl = 2 * tx;
            int pos = (kl & ~15) + ppos(kl & 15);
            *(uint32_t*)&outp[(size_t)(n0 + n) * K + k0 + pos] =
                h2u(t[kl][n], t[kl + 1][n]);
        }
    }
}

// ---------------- fp16 tensor-core flash attention --------------------------
// Split commit groups: KV (16KB) then bias (36.9KB) per tile. S-mma waits
// only on KV; bias tail overlaps the S-mma chain. Two barriers per tile.
#define ASTG 53248
#define NTILES (NT / 64)
__global__ __launch_bounds__(256, 2) void attn_h(
    const __half* __restrict__ Q, const __half* __restrict__ Kpk,
    const __half* __restrict__ Vpk, const float* __restrict__ bias,
    __half* __restrict__ O16)
{
    extern __shared__ char smc[];
    const int tid = threadIdx.x;
    const int lane = tid & 31;
    const int g = lane >> 2, c = lane & 3;
    const int h = blockIdx.y;
    const int q0 = blockIdx.x * 128;
    const int r0 = 16 * (tid >> 5) + g;
    const unsigned sbase = (unsigned)__cvta_generic_to_shared(smc);
    const uint32_t ONES2 = 0x3C003C00u;

    uint32_t qa[4][4];
    {
        const char* qp0 = (const char*)(Q + (size_t)(q0 + r0) * DM + h * HD);
        const char* qp1 = qp0 + (size_t)8 * DM * 2;
#pragma unroll
        for (int kk = 0; kk < 4; kk++) {
            uint2 t0 = *(const uint2*)(qp0 + kk * 32 + c * 8);
            uint2 t1 = *(const uint2*)(qp1 + kk * 32 + c * 8);
            qa[kk][0] = t0.x; qa[kk][1] = t1.x; qa[kk][2] = t0.y; qa[kk][3] = t1.y;
        }
    }

    float o[8][4];
#pragma unroll
    for (int j = 0; j < 8; j++)
#pragma unroll
        for (int r = 0; r < 4; r++) o[j][r] = 0.f;
    float lacc[4] = {0.f, 0.f, 0.f, 0.f};
    float mr0 = -1e30f, mr1 = -1e30f;

    const __half* kbase = Kpk + (size_t)h * NT * 64;
    const __half* vbase = Vpk + (size_t)h * NT * 64;
    const float*  bbase = bias + ((size_t)h * NT + q0) * NT;

    auto stage_kv = [&](int t) {
        const unsigned s0 = sbase + (t & 1) * ASTG;
        const char* ks = (const char*)(kbase + (size_t)t * 4096);
        const char* vs = (const char*)(vbase + (size_t)t * 4096);
        cpa16(s0 + tid * 16,         ks + tid * 16);
        cpa16(s0 + 4096 + tid * 16,  ks + 4096 + tid * 16);
        cpa16(s0 + 8192 + tid * 16,  vs + tid * 16);
        cpa16(s0 + 12288 + tid * 16, vs + 4096 + tid * 16);
        asm volatile("cp.async.commit_group;" ::: "memory");
    };
    auto stage_bias = [&](int t) {
        const unsigned s0 = sbase + (t & 1) * ASTG;
        const float* bsrc = bbase + t * 64;
#pragma unroll
        for (int i = 0; i < 8; i++) {
            int idx = i * 256 + tid;
            int row = idx >> 4, cc = idx & 15;
            cpa16(s0 + 16384 + row * 288 + cc * 16,
                  bsrc + (size_t)row * NT + cc * 4);
        }
        asm volatile("cp.async.commit_group;" ::: "memory");
    };

    stage_kv(0);
    stage_bias(0);
    const int swz = (g & 1) << 6;

    for (int t = 0; t < NTILES; t++) {
        asm volatile("cp.async.wait_group 1;" ::: "memory");
        __syncthreads();
        if (t + 1 < NTILES) {
            stage_kv(t + 1);
            stage_bias(t + 1);
        }

        const char* Ksb = smc + (t & 1) * ASTG;
        const char* Vsb = Ksb + 8192;
        const char* Bsb = Ksb + 16384;

        float s[8][4];
#pragma unroll
        for (int j = 0; j < 8; j++) {
            s[j][0] = 0.f; s[j][1] = 0.f; s[j][2] = 0.f; s[j][3] = 0.f;
        }
#pragma unroll
        for (int kkp = 0; kkp < 2; kkp++) {
#pragma unroll
            for (int j = 0; j < 8; j++) {
                uint4 kb = *(const uint4*)(Ksb + (8 * j + g) * 128 + c * 16 + ((kkp << 6) ^ swz));
                mma16(s[j], qa[2 * kkp][0], qa[2 * kkp][1], qa[2 * kkp][2], qa[2 * kkp][3], kb.x, kb.y);
                mma16(s[j], qa[2 * kkp + 1][0], qa[2 * kkp + 1][1], qa[2 * kkp + 1][2], qa[2 * kkp + 1][3], kb.z, kb.w);
            }
        }

        if (t + 1 < NTILES) {
            asm volatile("cp.async.wait_group 2;" ::: "memory");
        } else {
            asm volatile("cp.async.wait_group 0;" ::: "memory");
        }
        __syncthreads();

        const char* br0 = Bsb + r0 * 288 + 8 * c;
        const char* br1 = Bsb + (r0 + 8) * 288 + 8 * c;
#pragma unroll
        for (int j = 0; j < 8; j++) {
            float2 b0 = *(const float2*)(br0 + 32 * j);
            float2 b1 = *(const float2*)(br1 + 32 * j);
            s[j][0] += b0.x; s[j][1] += b0.y; s[j][2] += b1.x; s[j][3] += b1.y;
        }

        float rm0 = -1e30f, rm1 = -1e30f;
#pragma unroll
        for (int j = 0; j < 8; j++) {
            rm0 = fmaxf(rm0, fmaxf(s[j][0], s[j][1]));
            rm1 = fmaxf(rm1, fmaxf(s[j][2], s[j][3]));
        }
        rm0 = fmaxf(rm0, __shfl_xor_sync(0xffffffffu, rm0, 1));
        rm0 = fmaxf(rm0, __shfl_xor_sync(0xffffffffu, rm0, 2));
        rm1 = fmaxf(rm1, __shfl_xor_sync(0xffffffffu, rm1, 1));
        rm1 = fmaxf(rm1, __shfl_xor_sync(0xffffffffu, rm1, 2));

        if (__any_sync(0xffffffffu, (rm0 > mr0) || (rm1 > mr1))) {
            float mn0 = fmaxf(mr0, rm0), mn1 = fmaxf(mr1, rm1);
            float corr0 = fexp(mr0 - mn0), corr1 = fexp(mr1 - mn1);
            mr0 = mn0; mr1 = mn1;
            lacc[0] *= corr0; lacc[1] *= corr0;
            lacc[2] *= corr1; lacc[3] *= corr1;
#pragma unroll
            for (int j = 0; j < 8; j++) {
                o[j][0] *= corr0; o[j][1] *= corr0;
                o[j][2] *= corr1; o[j][3] *= corr1;
            }
        }

        const float mlog0 = mr0 * LOG2E, mlog1 = mr1 * LOG2E;
        uint32_t pf[8][2];
#pragma unroll
        for (int j = 0; j < 8; j++) {
            float y00 = fmaf(s[j][0], LOG2E, -mlog0);
            float y01 = fmaf(s[j][1], LOG2E, -mlog0);
            float y10 = fmaf(s[j][2], LOG2E, -mlog1);
            float y11 = fmaf(s[j][3], LOG2E, -mlog1);
            pf[j][0] = ex2h2(h2u(y00, y01));
            pf[j][1] = ex2h2(h2u(y10, y11));
        }

#pragma unroll
        for (int tkp = 0; tkp < 2; tkp++) {
            uint32_t a00 = pf[4 * tkp + 0][0], a01 = pf[4 * tkp + 0][1];
            uint32_t a02 = pf[4 * tkp + 1][0], a03 = pf[4 * tkp + 1][1];
            uint32_t a10 = pf[4 * tkp + 2][0], a11 = pf[4 * tkp + 2][1];
            uint32_t a12 = pf[4 * tkp + 3][0], a13 = pf[4 * tkp + 3][1];
            mma16(lacc, a00, a01, a02, a03, ONES2, ONES2);
            mma16(lacc, a10, a11, a12, a13, ONES2, ONES2);
#pragma unroll
            for (int j = 0; j < 8; j++) {
                uint4 vb = *(const uint4*)(Vsb + (8 * j + g) * 128 + c * 16 + ((tkp << 6) ^ swz));
                mma16(o[j], a00, a01, a02, a03, vb.x, vb.y);
                mma16(o[j], a10, a11, a12, a13, vb.z, vb.w);
            }
        }
    }

    float inv0 = 1.0f / lacc[0], inv1 = 1.0f / lacc[2];
    const int grow0 = q0 + r0;
#pragma unroll
    for (int j = 0; j < 8; j++) {
        int col = h * HD + 8 * j + 2 * c;
        size_t p = (size_t)grow0 * DM + (col & ~15) + ppos(col & 15);
        *(uint32_t*)&O16[p]                  = h2u(o[j][0] * inv0, o[j][1] * inv0);
        *(uint32_t*)&O16[p + (size_t)8 * DM] = h2u(o[j][2] * inv1, o[j][3] * inv1);
    }
}

// ---------------- warp-per-row residual + LayerNorm -------------------------
template <bool PACK>
__global__ __launch_bounds__(256) void add_ln(
    const float* __restrict__ A, const float* __restrict__ B,
    const float* __restrict__ g, const float* __restrict__ be,
    float* __restrict__ out, __half* __restrict__ out16)
{
    const int row = blockIdx.x * 8 + (threadIdx.x >> 5);
    const int lane = threadIdx.x & 31;
    const float* ap = A + (size_t)row * DM;
    const float* bp = B + (size_t)row * DM;

    float4 v[4];
    float s = 0.f;
#pragma unroll
    for (int i = 0; i < 4; i++) {
        int col = (i * 32 + lane) * 4;
        float4 a = *(const float4*)(ap + col);
        float4 b = *(const float4*)(bp + col);
        v[i] = make_float4(a.x + b.x, a.y + b.y, a.z + b.z, a.w + b.w);
        s += v[i].x + v[i].y + v[i].z + v[i].w;
    }
#pragma unroll
    for (int off = 16; off; off >>= 1) s += __shfl_xor_sync(0xffffffffu, s, off);
    float mu = s * (1.f / DM);

    float sq = 0.f;
#pragma unroll
    for (int i = 0; i < 4; i++) {
        v[i].x -= mu; v[i].y -= mu; v[i].z -= mu; v[i].w -= mu;
        sq += v[i].x * v[i].x + v[i].y * v[i].y + v[i].z * v[i].z + v[i].w * v[i].w;
    }
#pragma unroll
    for (int off = 16; off; off >>= 1) sq += __shfl_xor_sync(0xffffffffu, sq, off);
    float inv = rsqrtf(sq * (1.f / DM) + 1e-5f);

#pragma unroll
    for (int i = 0; i < 4; i++) {
        int col = (i * 32 + lane) * 4;
        float4 gg = *(const float4*)(g + col);
        float4 bb = *(const float4*)(be + col);
        float4 r;
        r.x = v[i].x * inv * gg.x + bb.x;
        r.y = v[i].y * inv * gg.y + bb.y;
        r.z = v[i].z * inv * gg.z + bb.z;
        r.w = v[i].w * inv * gg.w + bb.w;
        *(float4*)(out + (size_t)row * DM + col) = r;
        if (PACK) {
            size_t base = (size_t)row * DM + (col & ~15);
            *(uint32_t*)&out16[base + ppos(col & 15)]       = h2u(r.x, r.y);
            *(uint32_t*)&out16[base + ppos((col + 2) & 15)] = h2u(r.z, r.w);
        }
    }
}

// ---------------- launch ----------------------------------------------------
extern "C" void kernel_launch(void* const* d_in, const int* in_sizes, int n_in,
                              void* d_out, int out_size)
{
    const float* x    = (const float*)d_in[0];
    const float* bias = (const float*)d_in[1];
    const float* Wq = (const float*)d_in[2];  const float* bq = (const float*)d_in[3];
    const float* Wk = (const float*)d_in[4];  const float* bk = (const float*)d_in[5];
    const float* Wv = (const float*)d_in[6];  const float* bv = (const float*)d_in[7];
    const float* Wo = (const float*)d_in[8];  const float* bo = (const float*)d_in[9];
    const float* g1 = (const float*)d_in[10]; const float* b1 = (const float*)d_in[11];
    const float* g2 = (const float*)d_in[12]; const float* b2 = (const float*)d_in[13];
    const float* W1 = (const float*)d_in[14]; const float* c1 = (const float*)d_in[15];
    const float* W2 = (const float*)d_in[16]; const float* c2 = (const float*)d_in[17];
    float* out = (float*)d_out;

    __half *Qp, *Kp, *Vp, *x16p, *attn16p, *x116p, *hid16p;
    __half *WqT, *WkT, *WvT, *WoT, *W1T, *W2T;
    float *tmpp, *x1p;
    cudaGetSymbolAddress((void**)&Qp,     g_Q);
    cudaGetSymbolAddress((void**)&Kp,     g_K);
    cudaGetSymbolAddress((void**)&Vp,     g_V);
    cudaGetSymbolAddress((void**)&x16p,   g_x16);
    cudaGetSymbolAddress((void**)&attn16p, g_attn16);
    cudaGetSymbolAddress((void**)&x116p,  g_x116);
    cudaGetSymbolAddress((void**)&hid16p, g_hid16);
    cudaGetSymbolAddress((void**)&tmpp,   g_tmp);
    cudaGetSymbolAddress((void**)&x1p,    g_x1);
    cudaGetSymbolAddress((void**)&WqT,    g_WqT);
    cudaGetSymbolAddress((void**)&WkT,    g_WkT);
    cudaGetSymbolAddress((void**)&WvT,    g_WvT);
    cudaGetSymbolAddress((void**)&WoT,    g_WoT);
    cudaGetSymbolAddress((void**)&W1T,    g_W1T);
    cudaGetSymbolAddress((void**)&W2T,    g_W2T);

    const int ATTN_SMEM = 2 * ASTG;   // 106496
    cudaFuncSetAttribute(attn_h, cudaFuncAttributeMaxDynamicSharedMemorySize, ATTN_SMEM);

    pack_x<<<NT * DM / 16 / 256, 256>>>(x, x16p);
    transpose_all<<<dim3(DFF / 32, DFF / 32, 6), 256>>>(
        Wq, Wk, Wv, Wo, W1, W2, WqT, WkT, WvT, WoT, W1T, W2T);

    dim3 blk(256);
    qkv16<<<dim3(DM / 128, NT / 64, 3), blk>>>(
        x16p, WqT, bq, Qp, WkT, bk, Kp, WvT, bv, Vp);

    attn_h<<<dim3(NT / 128, NH), blk, ATTN_SMEM>>>(Qp, Kp, Vp, bias, attn16p);

    gemm16<0><<<dim3(DM / 128, NT / 64), blk>>>(attn16p, WoT, bo, tmpp, DM, DM);
    add_ln<true><<<NT / 8, 256>>>(x, tmpp, g1, b1, x1p, x116p);

    gemm16<1><<<dim3(DFF / 128, NT / 64), blk>>>(x116p, W1T, c1, hid16p, DFF, DM);
    gemm16<0><<<dim3(DM / 128, NT / 64), blk>>>(hid16p, W2T, c2, tmpp, DM, DFF);
    add_ln<false><<<NT / 8, 256>>>(x1p, tmpp, g2, b2, out, nullptr);
}